// round 15
// baseline (speedup 1.0000x reference)
#include <cuda_runtime.h>
#include <cuda_fp16.h>
#include <cstdint>

#define H 40
#define T 256
#define BATCH 8192
#define EPB 32
#define THREADS 320             // 10 warps: mt 0..1 x ng 0..4, 4 n-tiles per warp
#define NWARPS 10
#define NBLOCKS (BATCH / EPB)   // 256

#define PITCH 88                // fp16 cols per element row (h1 0..39 | h2 40..79 | x 80..82 | pad)
#define NFRAG 160               // L1: 3kt x 20nt ; L2: 5kt x 20nt
#define OFF_BF 0
#define BF_BYTES (NFRAG * 32 * 8)           // 40960 (uint2 per lane)
#define OFF_HSHI BF_BYTES
#define HS_BYTES (2 * EPB * PITCH * 2)      // 11264 (2 buffers, hi only)
#define OFF_B1S  (OFF_HSHI + HS_BYTES)      // float[160]
#define OFF_B2S  (OFF_B1S + 640)
#define SMEM_BYTES (OFF_B2S + 640)          // 53504 -> 2 CTAs/SM

__device__ __forceinline__ float tanhfast(float x) {
    float y; asm("tanh.approx.f32 %0, %1;" : "=f"(y) : "f"(x)); return y;
}
__device__ __forceinline__ float sigf(float x) {
    return fmaf(0.5f, tanhfast(0.5f * x), 0.5f);
}
__device__ __forceinline__ uint32_t packh(__half a, __half b) {
    __half2 t; t.x = a; t.y = b;
    return *(uint32_t*)&t;
}
__device__ __forceinline__ void mma16816h(float* d, const uint32_t* a, uint32_t b0, uint32_t b1) {
    asm("mma.sync.aligned.m16n8k16.row.col.f32.f16.f16.f32 "
        "{%0,%1,%2,%3},{%4,%5,%6,%7},{%8,%9},{%0,%1,%2,%3};"
        : "+f"(d[0]), "+f"(d[1]), "+f"(d[2]), "+f"(d[3])
        : "r"(a[0]), "r"(a[1]), "r"(a[2]), "r"(a[3]), "r"(b0), "r"(b1));
}

__global__ __launch_bounds__(THREADS, 2)
void lstm2_tc6_kernel(const float* __restrict__ x,
                      const float* __restrict__ W_ih1,
                      const float* __restrict__ W_hh1,
                      const float* __restrict__ b1,
                      const float* __restrict__ W_ih2,
                      const float* __restrict__ W_hh2,
                      const float* __restrict__ b2,
                      const float* __restrict__ W_fc,
                      const float* __restrict__ b_fc,
                      float* __restrict__ out)
{
    extern __shared__ char smem[];
    uint2* __restrict__ BF = (uint2*)(smem + OFF_BF);
    __half* __restrict__ HShi = (__half*)(smem + OFF_HSHI);
    float* __restrict__ B1S = (float*)(smem + OFF_B1S);
    float* __restrict__ B2S = (float*)(smem + OFF_B2S);

    const int tid  = threadIdx.x;
    const int w    = tid >> 5;
    const int lane = tid & 31;
    const int gid  = lane >> 2;     // 0..7
    const int tig  = lane & 3;      // 0..3
    const int mt   = (w >= 5) ? 1 : 0;      // m-tile (16 elements)
    const int ng   = (w >= 5) ? (w - 5) : w; // 0..4 : n-tiles ng*4 .. ng*4+3

    const float* xp = x + ((long)blockIdx.x * EPB + (tid & 31)) * (T * 3);

    // ---------------- init: zero both HS buffers; bias tables ----------------
    for (int i = tid; i < 2 * EPB * PITCH; i += THREADS) {
        HShi[i] = __float2half(0.0f);
    }
    for (int n = tid; n < 160; n += THREADS) {
        int r = (n & 3) * H + (n >> 2);
        B1S[n] = __ldg(b1 + r);
        B2S[n] = __ldg(b2 + r);
    }
    // ---------------- init: pack B fragments (fp16) ----------------
    for (int f = w; f < NFRAG; f += NWARPS) {
        int layer, kt, nt;
        if (f < 60) { layer = 0; kt = f / 20; nt = f % 20; }
        else        { layer = 1; kt = (f - 60) / 20; nt = (f - 60) % 20; }
        int n = nt * 8 + gid;
        int r = (n & 3) * H + (n >> 2);   // PyTorch row = gate*H + unit
        float v[4];
        #pragma unroll
        for (int q = 0; q < 4; q++) {
            int k = kt * 16 + 2 * tig + ((q >> 1) * 8) + (q & 1);
            float val;
            if (layer == 0) {
                if (k < 40)      val = W_hh1[r * H + k];
                else if (k < 43) val = W_ih1[r * 3 + (k - 40)];
                else             val = 0.0f;          // bias folded into D-init
            } else {
                if (k < 40)      val = W_ih2[r * H + k];
                else             val = W_hh2[r * H + (k - 40)];
            }
            v[q] = val;
        }
        uint2 pk;
        pk.x = packh(__float2half_rn(v[0]), __float2half_rn(v[1]));
        pk.y = packh(__float2half_rn(v[2]), __float2half_rn(v[3]));
        BF[f * 32 + lane] = pk;
    }
    __syncthreads();
    // stage x(0) -> buf0, x(1) -> buf1
    if (tid < EPB) {
        #pragma unroll
        for (int bu = 0; bu < 2; bu++) {
            #pragma unroll
            for (int c = 0; c < 3; c++) {
                HShi[bu * EPB * PITCH + tid * PITCH + 80 + c] =
                    __float2half_rn(__ldg(xp + bu * 3 + c));
            }
        }
    }
    __syncthreads();

    // ---------------- recurrent state ----------------
    float cs1[4][2], cs2[4][2];
    #pragma unroll
    for (int i = 0; i < 4; i++) {
        cs1[i][0] = cs1[i][1] = 0.0f;
        cs2[i][0] = cs2[i][1] = 0.0f;
    }

    const int e0 = mt * 16 + gid;
    const int e1 = e0 + 8;
    const int nbase = (ng * 4) * 8 + 2 * tig;

    auto epi = [&](float D[4][4], float cs[4][2], __half* Whi, int colbase) {
        #pragma unroll
        for (int ntl = 0; ntl < 4; ntl++) {
            float u0, v0, u1, v1;
            if ((tig & 1) == 0) {
                u0 = sigf(D[ntl][0]); v0 = sigf(D[ntl][1]);
                u1 = sigf(D[ntl][2]); v1 = sigf(D[ntl][3]);
            } else {
                u0 = tanhfast(D[ntl][0]); v0 = sigf(D[ntl][1]);
                u1 = tanhfast(D[ntl][2]); v1 = sigf(D[ntl][3]);
            }
            float g0 = __shfl_xor_sync(0xffffffffu, u0, 1);
            float g1 = __shfl_xor_sync(0xffffffffu, u1, 1);
            cs[ntl][0] = fmaf(v0, cs[ntl][0], u0 * g0);
            cs[ntl][1] = fmaf(v1, cs[ntl][1], u1 * g1);
            float tc0 = tanhfast(cs[ntl][0]);
            float tc1 = tanhfast(cs[ntl][1]);
            float r0 = __shfl_xor_sync(0xffffffffu, tc0, 1);
            float r1 = __shfl_xor_sync(0xffffffffu, tc1, 1);
            if (tig & 1) {
                int unit = 2 * (ng * 4 + ntl) + (tig >> 1);
                Whi[e0 * PITCH + colbase + unit] = __float2half_rn(v0 * r0);
                Whi[e1 * PITCH + colbase + unit] = __float2half_rn(v1 * r1);
            }
        }
    };

    for (int t = 0; t < T; t++) {
        const int p = t & 1;
        __half* Phi = HShi + p * EPB * PITCH;         // buf[p]: this step's writes, x(t)
        __half* Qhi = HShi + (1 - p) * EPB * PITCH;   // buf[1-p]: h1(t-1), h2(t-1)

        // global prefetch of x(t+2)
        float xr0 = 0.f, xr1 = 0.f, xr2 = 0.f;
        if (tid < EPB) {
            int tn = (t + 2 < T) ? (t + 2) : (T - 1);
            xr0 = __ldg(xp + tn * 3 + 0);
            xr1 = __ldg(xp + tn * 3 + 1);
            xr2 = __ldg(xp + tn * 3 + 2);
        }

        float D[4][4];

        // ================= P1: L1 MMA  (A = [h1(t-1) | x(t)]) =================
        #pragma unroll
        for (int ntl = 0; ntl < 4; ntl++) {
            float bb0 = B1S[nbase + ntl * 8];
            float bb1 = B1S[nbase + ntl * 8 + 1];
            D[ntl][0] = bb0; D[ntl][1] = bb1;
            D[ntl][2] = bb0; D[ntl][3] = bb1;
        }
        #pragma unroll
        for (int kt = 0; kt < 3; kt++) {
            const int c0 = (kt < 2) ? kt * 16 + 2 * tig : 32 + 2 * tig;
            const int c8 = (kt < 2) ? kt * 16 + 8 + 2 * tig : 80 + 2 * tig;
            const __half* s8hi = (kt < 2) ? Qhi : Phi;   // x(t) lives in buf[p]
            uint32_t ah[4];
            ah[0] = *(const uint32_t*)(Qhi + e0 * PITCH + c0);
            ah[1] = *(const uint32_t*)(Qhi + e1 * PITCH + c0);
            ah[2] = *(const uint32_t*)(s8hi + e0 * PITCH + c8);
            ah[3] = *(const uint32_t*)(s8hi + e1 * PITCH + c8);
            #pragma unroll
            for (int ntl = 0; ntl < 4; ntl++) {
                uint2 bb = BF[(kt * 20 + ng * 4 + ntl) * 32 + lane];
                mma16816h(D[ntl], ah, bb.x, bb.y);
            }
        }
        // epi1: write h1(t) -> buf[p] cols 0..39
        epi(D, cs1, Phi, 0);
        __syncthreads();

        // stage x(t+2) -> buf[p] cols 80..82 (x(t) readers finished pre-BAR)
        if (tid < EPB) {
            Phi[tid * PITCH + 80] = __float2half_rn(xr0);
            Phi[tid * PITCH + 81] = __float2half_rn(xr1);
            Phi[tid * PITCH + 82] = __float2half_rn(xr2);
        }

        // ================= P3: L2 MMA  (A = [h1(t) | h2(t-1)]) =================
        #pragma unroll
        for (int ntl = 0; ntl < 4; ntl++) {
            float bb0 = B2S[nbase + ntl * 8];
            float bb1 = B2S[nbase + ntl * 8 + 1];
            D[ntl][0] = bb0; D[ntl][1] = bb1;
            D[ntl][2] = bb0; D[ntl][3] = bb1;
        }
        #pragma unroll
        for (int kt = 0; kt < 5; kt++) {
            const int c0 = kt * 16 + 2 * tig;
            const int c8 = kt * 16 + 8 + 2 * tig;
            // cols < 40 = h1(t) in buf[p]; cols >= 40 = h2(t-1) in buf[1-p]
            const __half* s0hi = (kt <= 2) ? Phi : Qhi;
            const __half* s8hi = (kt < 2) ? Phi : Qhi;
            uint32_t ah[4];
            ah[0] = *(const uint32_t*)(s0hi + e0 * PITCH + c0);
            ah[1] = *(const uint32_t*)(s0hi + e1 * PITCH + c0);
            ah[2] = *(const uint32_t*)(s8hi + e0 * PITCH + c8);
            ah[3] = *(const uint32_t*)(s8hi + e1 * PITCH + c8);
            #pragma unroll
            for (int ntl = 0; ntl < 4; ntl++) {
                uint2 bb = BF[((60 + kt * 20) + ng * 4 + ntl) * 32 + lane];
                mma16816h(D[ntl], ah, bb.x, bb.y);
            }
        }
        // epi2: write h2(t) -> buf[p] cols 40..79 (next readers cross >=1 BAR)
        epi(D, cs2, Phi, 40);
    }
    __syncthreads();

    // ---------------- FC epilogue (h2(T-1) in buf[(T-1)&1] = buf1) ----------------
    if (tid < 2 * EPB) {
        int e = tid >> 1, q = tid & 1;
        const __half* Fhi = HShi + 1 * EPB * PITCH;
        float acc = __ldg(b_fc + q);
        #pragma unroll 8
        for (int u = 0; u < H; u++) {
            acc = fmaf(__half2float(Fhi[e * PITCH + 40 + u]), __ldg(W_fc + q * H + u), acc);
        }
        out[((long)blockIdx.x * EPB + e) * 2 + q] = acc;
    }
}

extern "C" void kernel_launch(void* const* d_in, const int* in_sizes, int n_in,
                              void* d_out, int out_size)
{
    const float* x     = (const float*)d_in[0];
    const float* W_ih1 = (const float*)d_in[1];
    const float* W_hh1 = (const float*)d_in[2];
    const float* b1    = (const float*)d_in[3];
    const float* W_ih2 = (const float*)d_in[4];
    const float* W_hh2 = (const float*)d_in[5];
    const float* b2    = (const float*)d_in[6];
    const float* W_fc  = (const float*)d_in[7];
    const float* b_fc  = (const float*)d_in[8];
    float* out = (float*)d_out;

    cudaFuncSetAttribute(lstm2_tc6_kernel,
                         cudaFuncAttributeMaxDynamicSharedMemorySize, SMEM_BYTES);

    lstm2_tc6_kernel<<<NBLOCKS, THREADS, SMEM_BYTES>>>(
        x, W_ih1, W_hh1, b1, W_ih2, W_hh2, b2, W_fc, b_fc, out);
}

// round 16
// speedup vs baseline: 1.1605x; 1.1605x over previous
#include <cuda_runtime.h>
#include <cuda_fp16.h>
#include <cstdint>

#define H 40
#define T 256
#define BATCH 8192
#define EPB 32
#define THREADS 256
#define NBLOCKS (BATCH / EPB)   // 256

#define PITCH 88                // fp16 cols per element row (h1 0..39 | h2 40..79 | x 80..82 | pad)
#define NFRAG 160               // L1: 3kt x 20nt ; L2: 5kt x 20nt
#define OFF_BF 0
#define BF_BYTES (NFRAG * 32 * 8)           // 40960 (uint2 per lane)
#define OFF_HSHI BF_BYTES
#define HS_BYTES (2 * EPB * PITCH * 2)      // 11264 (2 buffers, hi only)
#define OFF_B1S  (OFF_HSHI + HS_BYTES)      // float[160]
#define OFF_B2S  (OFF_B1S + 640)
#define SMEM_BYTES (OFF_B2S + 640)          // 53504 -> 2 CTAs/SM

__device__ __forceinline__ float tanhfast(float x) {
    float y; asm("tanh.approx.f32 %0, %1;" : "=f"(y) : "f"(x)); return y;
}
__device__ __forceinline__ float sigf(float x) {
    return fmaf(0.5f, tanhfast(0.5f * x), 0.5f);
}
__device__ __forceinline__ uint32_t packh(__half a, __half b) {
    __half2 t; t.x = a; t.y = b;
    return *(uint32_t*)&t;
}
__device__ __forceinline__ void mma16816h(float* d, const uint32_t* a, uint32_t b0, uint32_t b1) {
    asm("mma.sync.aligned.m16n8k16.row.col.f32.f16.f16.f32 "
        "{%0,%1,%2,%3},{%4,%5,%6,%7},{%8,%9},{%0,%1,%2,%3};"
        : "+f"(d[0]), "+f"(d[1]), "+f"(d[2]), "+f"(d[3])
        : "r"(a[0]), "r"(a[1]), "r"(a[2]), "r"(a[3]), "r"(b0), "r"(b1));
}

__global__ __launch_bounds__(THREADS, 2)
void lstm2_tc7_kernel(const float* __restrict__ x,
                      const float* __restrict__ W_ih1,
                      const float* __restrict__ W_hh1,
                      const float* __restrict__ b1,
                      const float* __restrict__ W_ih2,
                      const float* __restrict__ W_hh2,
                      const float* __restrict__ b2,
                      const float* __restrict__ W_fc,
                      const float* __restrict__ b_fc,
                      float* __restrict__ out)
{
    extern __shared__ char smem[];
    uint2* __restrict__ BF = (uint2*)(smem + OFF_BF);
    __half* __restrict__ HShi = (__half*)(smem + OFF_HSHI);
    float* __restrict__ B1S = (float*)(smem + OFF_B1S);
    float* __restrict__ B2S = (float*)(smem + OFF_B2S);

    const int tid  = threadIdx.x;
    const int w    = tid >> 5;
    const int lane = tid & 31;
    const int gid  = lane >> 2;     // 0..7
    const int tig  = lane & 3;      // 0..3
    const int mt   = w >> 2;        // 0..1 : m-tile (16 elements)
    const int ng   = w & 3;         // 0..3 : n-tiles ng*5 .. ng*5+4

    // x staging ownership: warp 0 -> rows 0..15, warp 4 -> rows 16..31 (lanes 0..15)
    const bool xw = (ng == 0) && (lane < 16);
    const int xe  = mt * 16 + (lane & 15);
    const float* xpe = x + ((long)blockIdx.x * EPB + xe) * (T * 3);
    const float* xp0 = x + ((long)blockIdx.x * EPB + (tid & 31)) * (T * 3);

    // ---------------- init: zero both HS buffers; bias tables ----------------
    for (int i = tid; i < 2 * EPB * PITCH; i += THREADS) {
        HShi[i] = __float2half(0.0f);
    }
    for (int n = tid; n < 160; n += THREADS) {
        int r = (n & 3) * H + (n >> 2);
        B1S[n] = __ldg(b1 + r);
        B2S[n] = __ldg(b2 + r);
    }
    // ---------------- init: pack B fragments (fp16) ----------------
    for (int f = w; f < NFRAG; f += 8) {
        int layer, kt, nt;
        if (f < 60) { layer = 0; kt = f / 20; nt = f % 20; }
        else        { layer = 1; kt = (f - 60) / 20; nt = (f - 60) % 20; }
        int n = nt * 8 + gid;
        int r = (n & 3) * H + (n >> 2);   // PyTorch row = gate*H + unit
        float v[4];
        #pragma unroll
        for (int q = 0; q < 4; q++) {
            int k = kt * 16 + 2 * tig + ((q >> 1) * 8) + (q & 1);
            float val;
            if (layer == 0) {
                if (k < 40)      val = W_hh1[r * H + k];
                else if (k < 43) val = W_ih1[r * 3 + (k - 40)];
                else             val = 0.0f;          // bias folded into D-init
            } else {
                if (k < 40)      val = W_ih2[r * H + k];
                else             val = W_hh2[r * H + (k - 40)];
            }
            v[q] = val;
        }
        uint2 pk;
        pk.x = packh(__float2half_rn(v[0]), __float2half_rn(v[1]));
        pk.y = packh(__float2half_rn(v[2]), __float2half_rn(v[3]));
        BF[f * 32 + lane] = pk;
    }
    __syncthreads();
    // stage x(0) -> buf0, x(1) -> buf1
    if (tid < EPB) {
        #pragma unroll
        for (int bu = 0; bu < 2; bu++) {
            #pragma unroll
            for (int c = 0; c < 3; c++) {
                HShi[bu * EPB * PITCH + tid * PITCH + 80 + c] =
                    __float2half_rn(__ldg(xp0 + bu * 3 + c));
            }
        }
    }
    __syncthreads();

    // ---------------- recurrent state ----------------
    float cs1[5][2], cs2[5][2];
    #pragma unroll
    for (int i = 0; i < 5; i++) {
        cs1[i][0] = cs1[i][1] = 0.0f;
        cs2[i][0] = cs2[i][1] = 0.0f;
    }

    const int e0 = mt * 16 + gid;
    const int e1 = e0 + 8;
    const int nbase = (ng * 5) * 8 + 2 * tig;

    auto epi = [&](float D[5][4], float cs[5][2], __half* Whi, int colbase) {
        #pragma unroll
        for (int ntl = 0; ntl < 5; ntl++) {
            float u0, v0, u1, v1;
            if ((tig & 1) == 0) {
                u0 = sigf(D[ntl][0]); v0 = sigf(D[ntl][1]);
                u1 = sigf(D[ntl][2]); v1 = sigf(D[ntl][3]);
            } else {
                u0 = tanhfast(D[ntl][0]); v0 = sigf(D[ntl][1]);
                u1 = tanhfast(D[ntl][2]); v1 = sigf(D[ntl][3]);
            }
            float g0 = __shfl_xor_sync(0xffffffffu, u0, 1);
            float g1 = __shfl_xor_sync(0xffffffffu, u1, 1);
            cs[ntl][0] = fmaf(v0, cs[ntl][0], u0 * g0);
            cs[ntl][1] = fmaf(v1, cs[ntl][1], u1 * g1);
            float tc0 = tanhfast(cs[ntl][0]);
            float tc1 = tanhfast(cs[ntl][1]);
            float r0 = __shfl_xor_sync(0xffffffffu, tc0, 1);
            float r1 = __shfl_xor_sync(0xffffffffu, tc1, 1);
            if (tig & 1) {
                int unit = 2 * (ng * 5 + ntl) + (tig >> 1);
                Whi[e0 * PITCH + colbase + unit] = __float2half_rn(v0 * r0);
                Whi[e1 * PITCH + colbase + unit] = __float2half_rn(v1 * r1);
            }
        }
    };

    for (int t = 0; t < T; t++) {
        const int p = t & 1;
        __half* Phi = HShi + p * EPB * PITCH;         // buf[p]: this step's writes, x(t)
        __half* Qhi = HShi + (1 - p) * EPB * PITCH;   // buf[1-p]: h1(t-1), h2(t-1)

        // global prefetch of x(t+2) (group-local staging warps)
        float xr0 = 0.f, xr1 = 0.f, xr2 = 0.f;
        if (xw) {
            int tn = (t + 2 < T) ? (t + 2) : (T - 1);
            xr0 = __ldg(xpe + tn * 3 + 0);
            xr1 = __ldg(xpe + tn * 3 + 1);
            xr2 = __ldg(xpe + tn * 3 + 2);
        }

        float D[5][4];

        // ================= P1: L1 MMA  (A = [h1(t-1) | x(t)]) =================
        #pragma unroll
        for (int ntl = 0; ntl < 5; ntl++) {
            float bb0 = B1S[nbase + ntl * 8];
            float bb1 = B1S[nbase + ntl * 8 + 1];
            D[ntl][0] = bb0; D[ntl][1] = bb1;
            D[ntl][2] = bb0; D[ntl][3] = bb1;
        }
        #pragma unroll
        for (int kt = 0; kt < 3; kt++) {
            const int c0 = (kt < 2) ? kt * 16 + 2 * tig : 32 + 2 * tig;
            const int c8 = (kt < 2) ? kt * 16 + 8 + 2 * tig : 80 + 2 * tig;
            const __half* s8hi = (kt < 2) ? Qhi : Phi;   // x(t) lives in buf[p]
            uint32_t ah[4];
            ah[0] = *(const uint32_t*)(Qhi + e0 * PITCH + c0);
            ah[1] = *(const uint32_t*)(Qhi + e1 * PITCH + c0);
            ah[2] = *(const uint32_t*)(s8hi + e0 * PITCH + c8);
            ah[3] = *(const uint32_t*)(s8hi + e1 * PITCH + c8);
            #pragma unroll
            for (int ntl = 0; ntl < 5; ntl++) {
                uint2 bb = BF[(kt * 20 + ng * 5 + ntl) * 32 + lane];
                mma16816h(D[ntl], ah, bb.x, bb.y);
            }
        }

        // pre-barrier prefetch of P3's kt=0 B fragments (barrier-independent)
        uint2 bf3[5];
        #pragma unroll
        for (int ntl = 0; ntl < 5; ntl++)
            bf3[ntl] = BF[(60 + ng * 5 + ntl) * 32 + lane];

        // epi1: write h1(t) -> buf[p] cols 0..39
        epi(D, cs1, Phi, 0);
        // per-m-tile barrier: the two 128-thread halves are fully disjoint in HS rows
        asm volatile("bar.sync %0, 128;" :: "r"(mt + 1) : "memory");

        // stage x(t+2) -> buf[p] cols 80..82 (x(t) readers of this group finished pre-BAR)
        if (xw) {
            Phi[xe * PITCH + 80] = __float2half_rn(xr0);
            Phi[xe * PITCH + 81] = __float2half_rn(xr1);
            Phi[xe * PITCH + 82] = __float2half_rn(xr2);
        }

        // ================= P3: L2 MMA  (A = [h1(t) | h2(t-1)]) =================
        #pragma unroll
        for (int ntl = 0; ntl < 5; ntl++) {
            float bb0 = B2S[nbase + ntl * 8];
            float bb1 = B2S[nbase + ntl * 8 + 1];
            D[ntl][0] = bb0; D[ntl][1] = bb1;
            D[ntl][2] = bb0; D[ntl][3] = bb1;
        }
        #pragma unroll
        for (int kt = 0; kt < 5; kt++) {
            const int c0 = kt * 16 + 2 * tig;
            const int c8 = kt * 16 + 8 + 2 * tig;
            // cols < 40 = h1(t) in buf[p]; cols >= 40 = h2(t-1) in buf[1-p]
            const __half* s0hi = (kt <= 2) ? Phi : Qhi;
            const __half* s8hi = (kt < 2) ? Phi : Qhi;
            uint32_t ah[4];
            ah[0] = *(const uint32_t*)(s0hi + e0 * PITCH + c0);
            ah[1] = *(const uint32_t*)(s0hi + e1 * PITCH + c0);
            ah[2] = *(const uint32_t*)(s8hi + e0 * PITCH + c8);
            ah[3] = *(const uint32_t*)(s8hi + e1 * PITCH + c8);
            #pragma unroll
            for (int ntl = 0; ntl < 5; ntl++) {
                uint2 bb = (kt == 0) ? bf3[ntl]
                                     : BF[((60 + kt * 20) + ng * 5 + ntl) * 32 + lane];
                mma16816h(D[ntl], ah, bb.x, bb.y);
            }
        }
        // epi2: write h2(t) -> buf[p] cols 40..79 (next readers cross >=1 group barrier)
        epi(D, cs2, Phi, 40);
    }
    __syncthreads();

    // ---------------- FC epilogue (h2(T-1) in buf[(T-1)&1] = buf1) ----------------
    if (tid < 2 * EPB) {
        int e = tid >> 1, q = tid & 1;
        const __half* Fhi = HShi + 1 * EPB * PITCH;
        float acc = __ldg(b_fc + q);
        #pragma unroll 8
        for (int u = 0; u < H; u++) {
            acc = fmaf(__half2float(Fhi[e * PITCH + 40 + u]), __ldg(W_fc + q * H + u), acc);
        }
        out[((long)blockIdx.x * EPB + e) * 2 + q] = acc;
    }
}

extern "C" void kernel_launch(void* const* d_in, const int* in_sizes, int n_in,
                              void* d_out, int out_size)
{
    const float* x     = (const float*)d_in[0];
    const float* W_ih1 = (const float*)d_in[1];
    const float* W_hh1 = (const float*)d_in[2];
    const float* b1    = (const float*)d_in[3];
    const float* W_ih2 = (const float*)d_in[4];
    const float* W_hh2 = (const float*)d_in[5];
    const float* b2    = (const float*)d_in[6];
    const float* W_fc  = (const float*)d_in[7];
    const float* b_fc  = (const float*)d_in[8];
    float* out = (float*)d_out;

    cudaFuncSetAttribute(lstm2_tc7_kernel,
                         cudaFuncAttributeMaxDynamicSharedMemorySize, SMEM_BYTES);

    lstm2_tc7_kernel<<<NBLOCKS, THREADS, SMEM_BYTES>>>(
        x, W_ih1, W_hh1, b1, W_ih2, W_hh2, b2, W_fc, b_fc, out);
}

// round 17
// speedup vs baseline: 1.2481x; 1.0754x over previous
#include <cuda_runtime.h>
#include <cuda_fp16.h>
#include <cstdint>

#define H 40
#define T 256
#define BATCH 8192
#define EPB 32
#define THREADS 256
#define NBLOCKS (BATCH / EPB)   // 256

#define PITCH 88                // fp16 cols per element row (h1 0..39 | h2 40..79 | x 80..82 | pad)
#define NFRAG 160               // L1: 3kt x 20nt ; L2: 5kt x 20nt
#define OFF_BF 0
#define BF_BYTES (NFRAG * 32 * 8)           // 40960 (uint2 per lane)
#define OFF_HSHI BF_BYTES
#define HS_BYTES (2 * EPB * PITCH * 2)      // 11264 (2 buffers, hi only)
#define OFF_B1S  (OFF_HSHI + HS_BYTES)      // float[160]
#define OFF_B2S  (OFF_B1S + 640)
#define SMEM_BYTES (OFF_B2S + 640)          // 53504 -> 2 CTAs/SM

__device__ __forceinline__ float tanhfast(float x) {
    float y; asm("tanh.approx.f32 %0, %1;" : "=f"(y) : "f"(x)); return y;
}
__device__ __forceinline__ float sigf(float x) {
    return fmaf(0.5f, tanhfast(0.5f * x), 0.5f);
}
__device__ __forceinline__ uint32_t packh(__half a, __half b) {
    __half2 t; t.x = a; t.y = b;
    return *(uint32_t*)&t;
}
__device__ __forceinline__ void mma16816h(float* d, const uint32_t* a, uint32_t b0, uint32_t b1) {
    asm("mma.sync.aligned.m16n8k16.row.col.f32.f16.f16.f32 "
        "{%0,%1,%2,%3},{%4,%5,%6,%7},{%8,%9},{%0,%1,%2,%3};"
        : "+f"(d[0]), "+f"(d[1]), "+f"(d[2]), "+f"(d[3])
        : "r"(a[0]), "r"(a[1]), "r"(a[2]), "r"(a[3]), "r"(b0), "r"(b1));
}

// column-gate remap: col group of 4 = (i, g, f, o) of one unit
// PyTorch gate rows: i=0, f=1, g=2, o=3  ->  remap[colgate] = {0, 2, 1, 3}
__device__ __forceinline__ int gate_row(int n) {
    static const int rm[4] = {0, 2, 1, 3};
    return rm[n & 3] * H + (n >> 2);
}

__global__ __launch_bounds__(THREADS, 2)
void lstm2_tc8_kernel(const float* __restrict__ x,
                      const float* __restrict__ W_ih1,
                      const float* __restrict__ W_hh1,
                      const float* __restrict__ b1,
                      const float* __restrict__ W_ih2,
                      const float* __restrict__ W_hh2,
                      const float* __restrict__ b2,
                      const float* __restrict__ W_fc,
                      const float* __restrict__ b_fc,
                      float* __restrict__ out)
{
    extern __shared__ char smem[];
    uint2* __restrict__ BF = (uint2*)(smem + OFF_BF);
    __half* __restrict__ HShi = (__half*)(smem + OFF_HSHI);
    float* __restrict__ B1S = (float*)(smem + OFF_B1S);
    float* __restrict__ B2S = (float*)(smem + OFF_B2S);

    const int tid  = threadIdx.x;
    const int w    = tid >> 5;
    const int lane = tid & 31;
    const int gid  = lane >> 2;     // 0..7
    const int tig  = lane & 3;      // 0..3
    const int mt   = w >> 2;        // 0..1 : m-tile (16 elements)
    const int ng   = w & 3;         // 0..3 : n-tiles ng*5 .. ng*5+4

    // x staging ownership: warp 0 -> rows 0..15, warp 4 -> rows 16..31 (lanes 0..15)
    const bool xw = (ng == 0) && (lane < 16);
    const int xe  = mt * 16 + (lane & 15);
    const float* xpe = x + ((long)blockIdx.x * EPB + xe) * (T * 3);
    const float* xp0 = x + ((long)blockIdx.x * EPB + (tid & 31)) * (T * 3);

    // ---------------- init: zero both HS buffers; bias tables ----------------
    for (int i = tid; i < 2 * EPB * PITCH; i += THREADS) {
        HShi[i] = __float2half(0.0f);
    }
    for (int n = tid; n < 160; n += THREADS) {
        int r = gate_row(n);
        B1S[n] = __ldg(b1 + r);
        B2S[n] = __ldg(b2 + r);
    }
    // ---------------- init: pack B fragments (fp16, remapped gate order) ----------------
    for (int f = w; f < NFRAG; f += 8) {
        int layer, kt, nt;
        if (f < 60) { layer = 0; kt = f / 20; nt = f % 20; }
        else        { layer = 1; kt = (f - 60) / 20; nt = (f - 60) % 20; }
        int n = nt * 8 + gid;
        int r = gate_row(n);
        float v[4];
        #pragma unroll
        for (int q = 0; q < 4; q++) {
            int k = kt * 16 + 2 * tig + ((q >> 1) * 8) + (q & 1);
            float val;
            if (layer == 0) {
                if (k < 40)      val = W_hh1[r * H + k];
                else if (k < 43) val = W_ih1[r * 3 + (k - 40)];
                else             val = 0.0f;          // bias folded into D-init
            } else {
                if (k < 40)      val = W_ih2[r * H + k];
                else             val = W_hh2[r * H + (k - 40)];
            }
            v[q] = val;
        }
        uint2 pk;
        pk.x = packh(__float2half_rn(v[0]), __float2half_rn(v[1]));
        pk.y = packh(__float2half_rn(v[2]), __float2half_rn(v[3]));
        BF[f * 32 + lane] = pk;
    }
    __syncthreads();
    // stage x(0) -> buf0, x(1) -> buf1
    if (tid < EPB) {
        #pragma unroll
        for (int bu = 0; bu < 2; bu++) {
            #pragma unroll
            for (int c = 0; c < 3; c++) {
                HShi[bu * EPB * PITCH + tid * PITCH + 80 + c] =
                    __float2half_rn(__ldg(xp0 + bu * 3 + c));
            }
        }
    }
    __syncthreads();

    // ---------------- recurrent state + hoisted biases ----------------
    float cs1[5][2], cs2[5][2];
    #pragma unroll
    for (int i = 0; i < 5; i++) {
        cs1[i][0] = cs1[i][1] = 0.0f;
        cs2[i][0] = cs2[i][1] = 0.0f;
    }

    const int e0 = mt * 16 + gid;
    const int e1 = e0 + 8;
    const int nbase = (ng * 5) * 8 + 2 * tig;

    float b1r[5][2], b2r[5][2];
    #pragma unroll
    for (int i = 0; i < 5; i++) {
        b1r[i][0] = B1S[nbase + i * 8];
        b1r[i][1] = B1S[nbase + i * 8 + 1];
        b2r[i][0] = B2S[nbase + i * 8];
        b2r[i][1] = B2S[nbase + i * 8 + 1];
    }

    // epilogue: even tig holds (i,g), odd tig holds (f,o) of the same unit.
    // even: p = sig(i)*tanh(g); one shfl ships p; odd: c = sig(f)*c + p, h = sig(o)*tanh(c).
    auto epi = [&](float D[5][4], float cs[5][2], __half* Whi, int colbase) {
        #pragma unroll
        for (int ntl = 0; ntl < 5; ntl++) {
            float s0 = 0.f, s1 = 0.f;
            if ((tig & 1) == 0) {
                s0 = sigf(D[ntl][0]) * tanhfast(D[ntl][1]);   // row e0: sig(i)*tanh(g)
                s1 = sigf(D[ntl][2]) * tanhfast(D[ntl][3]);   // row e1
            }
            float q0 = __shfl_xor_sync(0xffffffffu, s0, 1);
            float q1 = __shfl_xor_sync(0xffffffffu, s1, 1);
            if (tig & 1) {
                cs[ntl][0] = fmaf(sigf(D[ntl][0]), cs[ntl][0], q0);  // c = sig(f)*c + p
                cs[ntl][1] = fmaf(sigf(D[ntl][2]), cs[ntl][1], q1);
                float h0 = sigf(D[ntl][1]) * tanhfast(cs[ntl][0]);   // h = sig(o)*tanh(c)
                float h1 = sigf(D[ntl][3]) * tanhfast(cs[ntl][1]);
                int unit = 2 * (ng * 5 + ntl) + (tig >> 1);
                Whi[e0 * PITCH + colbase + unit] = __float2half_rn(h0);
                Whi[e1 * PITCH + colbase + unit] = __float2half_rn(h1);
            }
        }
    };

    for (int t = 0; t < T; t++) {
        const int p = t & 1;
        __half* Phi = HShi + p * EPB * PITCH;         // buf[p]: this step's writes, x(t)
        __half* Qhi = HShi + (1 - p) * EPB * PITCH;   // buf[1-p]: h1(t-1), h2(t-1)

        // global prefetch of x(t+2) (group-local staging warps)
        float xr0 = 0.f, xr1 = 0.f, xr2 = 0.f;
        if (xw) {
            int tn = (t + 2 < T) ? (t + 2) : (T - 1);
            xr0 = __ldg(xpe + tn * 3 + 0);
            xr1 = __ldg(xpe + tn * 3 + 1);
            xr2 = __ldg(xpe + tn * 3 + 2);
        }

        float D[5][4];

        // ================= P1: L1 MMA  (A = [h1(t-1) | x(t)]) =================
        #pragma unroll
        for (int ntl = 0; ntl < 5; ntl++) {
            D[ntl][0] = b1r[ntl][0]; D[ntl][1] = b1r[ntl][1];
            D[ntl][2] = b1r[ntl][0]; D[ntl][3] = b1r[ntl][1];
        }
        #pragma unroll
        for (int kt = 0; kt < 3; kt++) {
            const int c0 = (kt < 2) ? kt * 16 + 2 * tig : 32 + 2 * tig;
            const int c8 = (kt < 2) ? kt * 16 + 8 + 2 * tig : 80 + 2 * tig;
            const __half* s8hi = (kt < 2) ? Qhi : Phi;   // x(t) lives in buf[p]
            uint32_t ah[4];
            ah[0] = *(const uint32_t*)(Qhi + e0 * PITCH + c0);
            ah[1] = *(const uint32_t*)(Qhi + e1 * PITCH + c0);
            ah[2] = *(const uint32_t*)(s8hi + e0 * PITCH + c8);
            ah[3] = *(const uint32_t*)(s8hi + e1 * PITCH + c8);
            #pragma unroll
            for (int ntl = 0; ntl < 5; ntl++) {
                uint2 bb = BF[(kt * 20 + ng * 5 + ntl) * 32 + lane];
                mma16816h(D[ntl], ah, bb.x, bb.y);
            }
        }

        // pre-barrier prefetch of P3's kt=0 B fragments (barrier-independent)
        uint2 bf3[5];
        #pragma unroll
        for (int ntl = 0; ntl < 5; ntl++)
            bf3[ntl] = BF[(60 + ng * 5 + ntl) * 32 + lane];

        // epi1: write h1(t) -> buf[p] cols 0..39
        epi(D, cs1, Phi, 0);
        // per-m-tile barrier: the two 128-thread halves are fully disjoint in HS rows
        asm volatile("bar.sync %0, 128;" :: "r"(mt + 1) : "memory");

        // stage x(t+2) -> buf[p] cols 80..82 (x(t) readers of this group finished pre-BAR)
        if (xw) {
            Phi[xe * PITCH + 80] = __float2half_rn(xr0);
            Phi[xe * PITCH + 81] = __float2half_rn(xr1);
            Phi[xe * PITCH + 82] = __float2half_rn(xr2);
        }

        // ================= P3: L2 MMA  (A = [h1(t) | h2(t-1)]) =================
        #pragma unroll
        for (int ntl = 0; ntl < 5; ntl++) {
            D[ntl][0] = b2r[ntl][0]; D[ntl][1] = b2r[ntl][1];
            D[ntl][2] = b2r[ntl][0]; D[ntl][3] = b2r[ntl][1];
        }
        #pragma unroll
        for (int kt = 0; kt < 5; kt++) {
            const int c0 = kt * 16 + 2 * tig;
            const int c8 = kt * 16 + 8 + 2 * tig;
            // cols < 40 = h1(t) in buf[p]; cols >= 40 = h2(t-1) in buf[1-p]
            const __half* s0hi = (kt <= 2) ? Phi : Qhi;
            const __half* s8hi = (kt < 2) ? Phi : Qhi;
            uint32_t ah[4];
            ah[0] = *(const uint32_t*)(s0hi + e0 * PITCH + c0);
            ah[1] = *(const uint32_t*)(s0hi + e1 * PITCH + c0);
            ah[2] = *(const uint32_t*)(s8hi + e0 * PITCH + c8);
            ah[3] = *(const uint32_t*)(s8hi + e1 * PITCH + c8);
            #pragma unroll
            for (int ntl = 0; ntl < 5; ntl++) {
                uint2 bb = (kt == 0) ? bf3[ntl]
                                     : BF[((60 + kt * 20) + ng * 5 + ntl) * 32 + lane];
                mma16816h(D[ntl], ah, bb.x, bb.y);
            }
        }
        // epi2: write h2(t) -> buf[p] cols 40..79 (next readers cross >=1 group barrier)
        epi(D, cs2, Phi, 40);
    }
    __syncthreads();

    // ---------------- FC epilogue (h2(T-1) in buf[(T-1)&1] = buf1) ----------------
    if (tid < 2 * EPB) {
        int e = tid >> 1, q = tid & 1;
        const __half* Fhi = HShi + 1 * EPB * PITCH;
        float acc = __ldg(b_fc + q);
        #pragma unroll 8
        for (int u = 0; u < H; u++) {
            acc = fmaf(__half2float(Fhi[e * PITCH + 40 + u]), __ldg(W_fc + q * H + u), acc);
        }
        out[((long)blockIdx.x * EPB + e) * 2 + q] = acc;
    }
}

extern "C" void kernel_launch(void* const* d_in, const int* in_sizes, int n_in,
                              void* d_out, int out_size)
{
    const float* x     = (const float*)d_in[0];
    const float* W_ih1 = (const float*)d_in[1];
    const float* W_hh1 = (const float*)d_in[2];
    const float* b1    = (const float*)d_in[3];
    const float* W_ih2 = (const float*)d_in[4];
    const float* W_hh2 = (const float*)d_in[5];
    const float* b2    = (const float*)d_in[6];
    const float* W_fc  = (const float*)d_in[7];
    const float* b_fc  = (const float*)d_in[8];
    float* out = (float*)d_out;

    cudaFuncSetAttribute(lstm2_tc8_kernel,
                         cudaFuncAttributeMaxDynamicSharedMemorySize, SMEM_BYTES);

    lstm2_tc8_kernel<<<NBLOCKS, THREADS, SMEM_BYTES>>>(
        x, W_ih1, W_hh1, b1, W_ih2, W_hh2, b2, W_fc, b_fc, out);
}